// round 4
// baseline (speedup 1.0000x reference)
#include <cuda_runtime.h>
#include <math.h>

// Problem constants
#define BSZ   512
#define SEQ   100
#define DIM   16
#define F48   48
#define NH    36
#define ECOLS 1764        // 48*36 (E) + 36 (c)
#define COMB  176

// -------- scratch (__device__ globals: allocation-free) --------
// E stored as float4 groups: element addr = (i*9+kq)*2048 + b*4 + c, i in [0,48] (48 = c-vector)
__device__ float g_Ec[BSZ * ECOLS];
__device__ float g_coef[SEQ * BSZ];     // [s][b] masked scores (only kept s written/read)
__device__ int   g_skeep[SEQ];
__device__ int   g_any;
__device__ float g_y1[200 * BSZ];       // y1 transposed: [f][b]
__device__ float g_y2[80 * BSZ];        // y2 transposed: [f][b]

struct IdPtrs { const int* p[8]; };

// ============================================================================
// KA: one block. g_skeep[s] = OR_b (vg[b,s]==0); g_any = OR_s skeep.
// ============================================================================
__global__ void kA_mask(const int* __restrict__ vg) {
    __shared__ int flags[SEQ];
    int t = threadIdx.x;   // 1024
    if (t < SEQ) flags[t] = 0;
    __syncthreads();
    for (int p = t; p < BSZ * SEQ; p += 1024) {
        if (vg[p] == 0) atomicOr(&flags[p % SEQ], 1);
    }
    __syncthreads();
    if (t < SEQ) g_skeep[t] = flags[t];
    if (t == 0) {
        int a = 0;
        for (int s = 0; s < SEQ; s++) a |= flags[s];
        g_any = a;
    }
}

// ============================================================================
// K1: build E (and c) with b-innermost layout. Early-exit if !g_any.
// grid (56, 8), block 256 = 32 cols x 8 row-groups (8 b each -> 64 b / block)
// ============================================================================
__global__ void k1_EC(const float* __restrict__ table,
                      const int* __restrict__ ig, const int* __restrict__ ish,
                      const int* __restrict__ ic,
                      const float* __restrict__ W1, const float* __restrict__ b1) {
    if (g_any == 0) return;
    __shared__ float As[48][64];
    int tid = threadIdx.x;
    int b_base = blockIdx.y * 64;

    for (int p = tid; p < 48 * 64; p += 256) {
        int j = p >> 6, bl = p & 63;
        int which = j >> 4;
        int b = b_base + bl;
        int id = (which == 0) ? ig[b] : (which == 1) ? ish[b] : ic[b];
        As[j][bl] = table[(size_t)id * DIM + (j & 15)];
    }
    __syncthreads();

    int tx = tid & 31, ty = tid >> 5;
    int col = blockIdx.x * 32 + tx;
    if (col >= ECOLS) return;
    int b0 = ty * 8;

    float acc[8];
#pragma unroll
    for (int r = 0; r < 8; r++) acc[r] = 0.f;

    int ii, kk;
    if (col < 1728) {
        ii = col / 36; kk = col - ii * 36;
        const float* wp = W1 + (size_t)(144 + ii * 48) * 36 + kk;
#pragma unroll 4
        for (int j = 0; j < 48; j++) {
            float w = wp[j * 36];
            float4 a0 = *(const float4*)&As[j][b0];
            float4 a1 = *(const float4*)&As[j][b0 + 4];
            acc[0] += w * a0.x; acc[1] += w * a0.y; acc[2] += w * a0.z; acc[3] += w * a0.w;
            acc[4] += w * a1.x; acc[5] += w * a1.y; acc[6] += w * a1.z; acc[7] += w * a1.w;
        }
        float wcb = W1[(96 + ii) * 36 + kk] - W1[(48 + ii) * 36 + kk];
#pragma unroll
        for (int r = 0; r < 8; r++) acc[r] += wcb;
    } else {
        ii = 48; kk = col - 1728;
#pragma unroll 4
        for (int j = 0; j < 48; j++) {
            float w = W1[j * 36 + kk] + W1[(48 + j) * 36 + kk];
            float4 a0 = *(const float4*)&As[j][b0];
            float4 a1 = *(const float4*)&As[j][b0 + 4];
            acc[0] += w * a0.x; acc[1] += w * a0.y; acc[2] += w * a0.z; acc[3] += w * a0.w;
            acc[4] += w * a1.x; acc[5] += w * a1.y; acc[6] += w * a1.z; acc[7] += w * a1.w;
        }
        float bb = b1[kk];
#pragma unroll
        for (int r = 0; r < 8; r++) acc[r] += bb;
    }
    int kq = kk >> 2, c = kk & 3;
    size_t base = (size_t)(ii * 9 + kq) * 2048 + c;
#pragma unroll
    for (int r = 0; r < 8; r++)
        g_Ec[base + (size_t)(b_base + b0 + r) * 4] = acc[r];
}

// ============================================================================
// KB: fused activation unit per KEPT s: h (regs) + batch stats + dice + score
// + mask -> g_coef[s*512+b]. grid 100, block 512 (1 thread = 1 b). Early-exit.
// ============================================================================
__global__ __launch_bounds__(512) void kB_act(
        const float* __restrict__ table,
        const int* __restrict__ vg, const int* __restrict__ vsh,
        const int* __restrict__ vc,
        const float* __restrict__ alpha, const float* __restrict__ wout,
        const float* __restrict__ bout) {
    int s = blockIdx.x;
    if (!g_skeep[s]) return;
    int b = threadIdx.x;

    int id0 = vg[b * SEQ + s];
    int id1 = vsh[b * SEQ + s];
    int id2 = vc[b * SEQ + s];

    float vs[48];
    {
        const float4* r = (const float4*)(table + (size_t)id0 * DIM);
        float4 a = r[0], bb = r[1], cc = r[2], dd = r[3];
        vs[0]=a.x; vs[1]=a.y; vs[2]=a.z; vs[3]=a.w;
        vs[4]=bb.x; vs[5]=bb.y; vs[6]=bb.z; vs[7]=bb.w;
        vs[8]=cc.x; vs[9]=cc.y; vs[10]=cc.z; vs[11]=cc.w;
        vs[12]=dd.x; vs[13]=dd.y; vs[14]=dd.z; vs[15]=dd.w;
        r = (const float4*)(table + (size_t)id1 * DIM);
        a = r[0]; bb = r[1]; cc = r[2]; dd = r[3];
        vs[16]=a.x; vs[17]=a.y; vs[18]=a.z; vs[19]=a.w;
        vs[20]=bb.x; vs[21]=bb.y; vs[22]=bb.z; vs[23]=bb.w;
        vs[24]=cc.x; vs[25]=cc.y; vs[26]=cc.z; vs[27]=cc.w;
        vs[28]=dd.x; vs[29]=dd.y; vs[30]=dd.z; vs[31]=dd.w;
        r = (const float4*)(table + (size_t)id2 * DIM);
        a = r[0]; bb = r[1]; cc = r[2]; dd = r[3];
        vs[32]=a.x; vs[33]=a.y; vs[34]=a.z; vs[35]=a.w;
        vs[36]=bb.x; vs[37]=bb.y; vs[38]=bb.z; vs[39]=bb.w;
        vs[40]=cc.x; vs[41]=cc.y; vs[42]=cc.z; vs[43]=cc.w;
        vs[44]=dd.x; vs[45]=dd.y; vs[46]=dd.z; vs[47]=dd.w;
    }

    const float4* E4 = (const float4*)g_Ec;
    float h[36];
#pragma unroll
    for (int kq = 0; kq < 9; kq++) {
        float4 cv = E4[(size_t)(432 + kq) * 512 + b];
        h[kq*4+0]=cv.x; h[kq*4+1]=cv.y; h[kq*4+2]=cv.z; h[kq*4+3]=cv.w;
    }
    for (int i = 0; i < 48; i++) {
        float v = vs[i];
#pragma unroll
        for (int kq = 0; kq < 9; kq++) {
            float4 e = E4[(size_t)(i * 9 + kq) * 512 + b];
            h[kq*4+0] += v * e.x; h[kq*4+1] += v * e.y;
            h[kq*4+2] += v * e.z; h[kq*4+3] += v * e.w;
        }
    }

    // batch stats over the 512 threads, per k
    __shared__ float ps[36][16], pq[36][16];
    __shared__ float muS[36], isS[36];
    int w = b >> 5, lane = b & 31;
#pragma unroll
    for (int k = 0; k < 36; k++) {
        float sv = h[k], qv = h[k] * h[k];
#pragma unroll
        for (int o = 16; o; o >>= 1) {
            sv += __shfl_down_sync(0xffffffffu, sv, o);
            qv += __shfl_down_sync(0xffffffffu, qv, o);
        }
        if (lane == 0) { ps[k][w] = sv; pq[k][w] = qv; }
    }
    __syncthreads();
    if (b < 36) {
        float sv = 0.f, qv = 0.f;
#pragma unroll
        for (int j = 0; j < 16; j++) { sv += ps[b][j]; qv += pq[b][j]; }
        float mu = sv * (1.f / 512.f);
        float var = qv * (1.f / 512.f) - mu * mu;
        muS[b] = mu; isS[b] = rsqrtf(var + 1e-3f);
    }
    __syncthreads();

    float acc = bout[0];
#pragma unroll 4
    for (int k = 0; k < 36; k++) {
        float x = h[k];
        float xn = (x - muS[k]) * isS[k];
        float p = 1.f / (1.f + expf(-xn));
        acc += wout[k] * x * (p + alpha[k] * (1.f - p));
    }
    g_coef[s * 512 + b] = (id0 == 0) ? acc : 0.f;
}

// ============================================================================
// K5: build x in smem (profile gather + x_inter) + MLP1 GEMM + LN -> y1T[f][b].
// grid 32 (16 b each), block 256.
// ============================================================================
__global__ void k5_mlp1(const float* __restrict__ table, IdPtrs ids,
                        const int* __restrict__ vg, const int* __restrict__ vsh,
                        const int* __restrict__ vc,
                        const float* __restrict__ W, const float* __restrict__ bias,
                        const float* __restrict__ g, const float* __restrict__ beta) {
    __shared__ float xs[16 * COMB];
    __shared__ float ys[16 * 201];
    __shared__ float mu_s[16], isr_s[16];
    __shared__ int skeepS[SEQ];
    __shared__ int anyS;
    __shared__ float csh[16];
    int t = threadIdx.x;
    int b0 = blockIdx.x * 16;

    if (t == 0) anyS = g_any;
    if (t < SEQ) skeepS[t] = g_skeep[t];
    // profile gather: 16 b x 128 feats
    for (int p = t; p < 16 * 128; p += 256) {
        int bl = p >> 7, f = p & 127;
        int id = ids.p[f >> 4][b0 + bl];
        xs[bl * COMB + f] = table[(size_t)id * DIM + (f & 15)];
    }
    // zero x_inter region
    for (int p = t; p < 16 * 48; p += 256) {
        int bl = p / 48, i = p - bl * 48;
        xs[bl * COMB + 128 + i] = 0.f;
    }
    __syncthreads();

    if (anyS) {
        for (int s = 0; s < SEQ; s++) {
            if (!skeepS[s]) continue;
            if (t < 16) csh[t] = g_coef[s * 512 + b0 + t];
            __syncthreads();
            for (int e = t; e < 16 * 48; e += 256) {
                int bl = e / 48, i = e - bl * 48;
                float c = csh[bl];
                if (c != 0.f) {
                    int which = i >> 4;
                    int id = (which == 0) ? vg[(b0 + bl) * SEQ + s]
                           : (which == 1) ? vsh[(b0 + bl) * SEQ + s]
                                          : vc[(b0 + bl) * SEQ + s];
                    xs[bl * COMB + 128 + i] += c * table[(size_t)id * DIM + (i & 15)];
                }
            }
            __syncthreads();
        }
    }

    // GEMM: 200 features
    if (t < 200) {
        float acc[16];
        float bb = bias[t];
#pragma unroll
        for (int r = 0; r < 16; r++) acc[r] = bb;
        for (int j = 0; j < COMB; j++) {
            float w = W[j * 200 + t];
#pragma unroll
            for (int r = 0; r < 16; r++) acc[r] += w * xs[r * COMB + j];
        }
#pragma unroll
        for (int r = 0; r < 16; r++) ys[r * 201 + t] = acc[r];
    }
    __syncthreads();
    if (t < 16) {
        float s = 0.f, q = 0.f;
        for (int c = 0; c < 200; c++) { float v = ys[t * 201 + c]; s += v; q += v * v; }
        float mu = s * (1.f / 200.f);
        float var = q * (1.f / 200.f) - mu * mu;
        mu_s[t] = mu; isr_s[t] = rsqrtf(var + 1e-3f);
    }
    __syncthreads();
    if (t < 200) {
        float gg = g[t], be = beta[t];
#pragma unroll
        for (int r = 0; r < 16; r++)
            g_y1[(size_t)t * BSZ + b0 + r] = (ys[r * 201 + t] - mu_s[r]) * isr_s[r] * gg + be;
    }
}

// ============================================================================
// K7: redundant stats1 (coalesced from y1T) + dice + MLP2 GEMM + LN -> y2T.
// grid 16 (32 b each), block 256.
// ============================================================================
__global__ void k7_mlp2(const float* __restrict__ alpha1, const float* __restrict__ W,
                        const float* __restrict__ bias,
                        const float* __restrict__ g2, const float* __restrict__ be2) {
    __shared__ float mu1[200], is1[200];
    __shared__ float d1[200][32];
    __shared__ float ys[80][33];
    __shared__ float mu_b[32], isr_b[32];
    int t = threadIdx.x;
    int w = t >> 5, lane = t & 31;
    int b0 = blockIdx.x * 32;

    // stats over all 512 b for each of 200 features (coalesced rows of y1T)
    for (int rr = 0; rr < 25; rr++) {
        int f = w * 25 + rr;
        const float* row = g_y1 + (size_t)f * BSZ;
        float s = 0.f, q = 0.f;
#pragma unroll 4
        for (int i = 0; i < 16; i++) {
            float v = row[lane + 32 * i];
            s += v; q += v * v;
        }
#pragma unroll
        for (int o = 16; o; o >>= 1) {
            s += __shfl_down_sync(0xffffffffu, s, o);
            q += __shfl_down_sync(0xffffffffu, q, o);
        }
        if (lane == 0) {
            float mu = s * (1.f / 512.f);
            float var = q * (1.f / 512.f) - mu * mu;
            mu1[f] = mu; is1[f] = rsqrtf(var + 1e-3f);
        }
    }
    __syncthreads();

    // diced inputs for this block's 32 b
    for (int e = t; e < 200 * 32; e += 256) {
        int j = e >> 5, bl = e & 31;
        float v = g_y1[(size_t)j * BSZ + b0 + bl];
        float xn = (v - mu1[j]) * is1[j];
        float p = 1.f / (1.f + expf(-xn));
        d1[j][bl] = v * (p + alpha1[j] * (1.f - p));
    }
    __syncthreads();

    // GEMM: 80 out-features x 32 b; 160 active threads, 16 b each
    if (t < 160) {
        int f = t % 80, grp = t / 80;
        float acc[16];
        float bb = bias[f];
#pragma unroll
        for (int r = 0; r < 16; r++) acc[r] = bb;
        for (int j = 0; j < 200; j++) {
            float w2 = W[j * 80 + f];
#pragma unroll
            for (int r = 0; r < 16; r++) acc[r] += w2 * d1[j][grp * 16 + r];
        }
#pragma unroll
        for (int r = 0; r < 16; r++) ys[f][grp * 16 + r] = acc[r];
    }
    __syncthreads();
    if (t < 32) {
        float s = 0.f, q = 0.f;
        for (int c = 0; c < 80; c++) { float v = ys[c][t]; s += v; q += v * v; }
        float mu = s * (1.f / 80.f);
        float var = q * (1.f / 80.f) - mu * mu;
        mu_b[t] = mu; isr_b[t] = rsqrtf(var + 1e-3f);
    }
    __syncthreads();
    if (t < 160) {
        int f = t % 80, grp = t / 80;
        float gg = g2[f], be = be2[f];
#pragma unroll
        for (int r = 0; r < 16; r++) {
            int bl = grp * 16 + r;
            g_y2[(size_t)f * BSZ + b0 + bl] = (ys[f][bl] - mu_b[bl]) * isr_b[bl] * gg + be;
        }
    }
}

// ============================================================================
// K9: redundant stats2 (from y2T) + dice + out GEMM + softmax. grid 2, block 256.
// ============================================================================
__global__ void k9_out(const float* __restrict__ alpha2, const float* __restrict__ W,
                       const float* __restrict__ bout, float* __restrict__ out) {
    __shared__ float mu2[80], is2[80];
    int t = threadIdx.x;
    int w = t >> 5, lane = t & 31;
    int b0 = blockIdx.x * 256;

    for (int rr = 0; rr < 10; rr++) {
        int f = w * 10 + rr;
        const float* row = g_y2 + (size_t)f * BSZ;
        float s = 0.f, q = 0.f;
#pragma unroll 4
        for (int i = 0; i < 16; i++) {
            float v = row[lane + 32 * i];
            s += v; q += v * v;
        }
#pragma unroll
        for (int o = 16; o; o >>= 1) {
            s += __shfl_down_sync(0xffffffffu, s, o);
            q += __shfl_down_sync(0xffffffffu, q, o);
        }
        if (lane == 0) {
            float mu = s * (1.f / 512.f);
            float var = q * (1.f / 512.f) - mu * mu;
            mu2[f] = mu; is2[f] = rsqrtf(var + 1e-3f);
        }
    }
    __syncthreads();

    int b = b0 + t;
    float a0 = bout[0], a1 = bout[1];
#pragma unroll 4
    for (int f = 0; f < 80; f++) {
        float v = g_y2[(size_t)f * BSZ + b];
        float xn = (v - mu2[f]) * is2[f];
        float p = 1.f / (1.f + expf(-xn));
        float h = v * (p + alpha2[f] * (1.f - p));
        a0 += h * W[f * 2];
        a1 += h * W[f * 2 + 1];
    }
    float m = fmaxf(a0, a1);
    float e0 = expf(a0 - m), e1 = expf(a1 - m);
    float inv = 1.f / (e0 + e1);
    out[b * 2] = e0 * inv;
    out[b * 2 + 1] = e1 * inv;
}

// ============================================================================
extern "C" void kernel_launch(void* const* d_in, const int* in_sizes, int n_in,
                              void* d_out, int out_size) {
    (void)in_sizes; (void)n_in; (void)out_size;
    const int* uid  = (const int*)d_in[0];
    const int* ut1  = (const int*)d_in[1];
    const int* ut2  = (const int*)d_in[2];
    const int* ut3  = (const int*)d_in[3];
    const int* ut4  = (const int*)d_in[4];
    const int* ig   = (const int*)d_in[5];
    const int* ish  = (const int*)d_in[6];
    const int* ic   = (const int*)d_in[7];
    const int* vg   = (const int*)d_in[8];
    const int* vsh  = (const int*)d_in[9];
    const int* vc   = (const int*)d_in[10];
    const float* table     = (const float*)d_in[11];
    const float* W_act1    = (const float*)d_in[12];
    const float* b_act1    = (const float*)d_in[13];
    const float* alpha_act = (const float*)d_in[14];
    const float* W_act_out = (const float*)d_in[15];
    const float* b_act_out = (const float*)d_in[16];
    const float* W_mlp1    = (const float*)d_in[17];
    const float* b_mlp1    = (const float*)d_in[18];
    const float* g_ln1     = (const float*)d_in[19];
    const float* beta_ln1  = (const float*)d_in[20];
    const float* alpha_m1  = (const float*)d_in[21];
    const float* W_mlp2    = (const float*)d_in[22];
    const float* b_mlp2    = (const float*)d_in[23];
    const float* g_ln2     = (const float*)d_in[24];
    const float* beta_ln2  = (const float*)d_in[25];
    const float* alpha_m2  = (const float*)d_in[26];
    const float* W_out     = (const float*)d_in[27];
    const float* b_out     = (const float*)d_in[28];
    float* out = (float*)d_out;

    IdPtrs ids;
    ids.p[0] = uid; ids.p[1] = ut1; ids.p[2] = ut2; ids.p[3] = ut3;
    ids.p[4] = ut4; ids.p[5] = ig;  ids.p[6] = ish; ids.p[7] = ic;

    kA_mask<<<1, 1024>>>(vg);
    k1_EC<<<dim3(56, 8), 256>>>(table, ig, ish, ic, W_act1, b_act1);
    kB_act<<<SEQ, 512>>>(table, vg, vsh, vc, alpha_act, W_act_out, b_act_out);
    k5_mlp1<<<32, 256>>>(table, ids, vg, vsh, vc, W_mlp1, b_mlp1, g_ln1, beta_ln1);
    k7_mlp2<<<16, 256>>>(alpha_m1, W_mlp2, b_mlp2, g_ln2, beta_ln2);
    k9_out<<<2, 256>>>(alpha_m2, W_out, b_out, out);
}

// round 5
// speedup vs baseline: 2.5191x; 2.5191x over previous
#include <cuda_runtime.h>
#include <math.h>

#define BSZ   512
#define SEQ   100
#define DIM   16
#define NH    36
#define ECOLS 1764        // 48*36 (E) + 36 (c)
#define COMB  176

// -------- scratch (__device__ globals: allocation-free) --------
__device__ __align__(16) float g_Ec[BSZ * ECOLS];      // [(i*9+kq)*2048 + b*4 + c]
__device__ __align__(16) float g_h[SEQ * NH * BSZ];    // h_pre [(s*36+k)*512 + b]
__device__ __align__(16) float g_coef[SEQ * BSZ];      // [s][b]
__device__ __align__(16) float g_y1[200 * BSZ];        // transposed [f][b]
__device__ __align__(16) float g_d1[200 * BSZ];        // dice(y1), [f][b]
__device__ __align__(16) float g_y2[80 * BSZ];         // transposed [f][b]
__device__ int g_skeep[SEQ];
__device__ int g_any;

struct IdPtrs { const int* p[8]; };

__device__ __forceinline__ float sigm(float x) {
    return __fdividef(1.f, 1.f + __expf(-x));
}

// ============================================================================
// KA: one block. skeep[s] = OR_b (vg[b,s]==0); g_any.
// ============================================================================
__global__ void kA_mask(const int* __restrict__ vg) {
    __shared__ int flags[SEQ];
    int t = threadIdx.x;   // 1024
    if (t < SEQ) flags[t] = 0;
    __syncthreads();
    const int4* v4 = (const int4*)vg;
    for (int p = t; p < (BSZ * SEQ) / 4; p += 1024) {
        int4 v = v4[p];
        int base = p * 4;
        if (v.x == 0) atomicOr(&flags[ base      % SEQ], 1);
        if (v.y == 0) atomicOr(&flags[(base + 1) % SEQ], 1);
        if (v.z == 0) atomicOr(&flags[(base + 2) % SEQ], 1);
        if (v.w == 0) atomicOr(&flags[(base + 3) % SEQ], 1);
    }
    __syncthreads();
    if (t < SEQ) g_skeep[t] = flags[t];
    if (t == 0) {
        int a = 0;
        for (int s = 0; s < SEQ; s++) a |= flags[s];
        g_any = a;
    }
}

// ============================================================================
// K1: build E (b-innermost float4 layout). Early-exit if !g_any.
// grid (56, 8), block 256
// ============================================================================
__global__ void k1_EC(const float* __restrict__ table,
                      const int* __restrict__ ig, const int* __restrict__ ish,
                      const int* __restrict__ ic,
                      const float* __restrict__ W1, const float* __restrict__ b1) {
    if (g_any == 0) return;
    __shared__ float As[48][64];
    int tid = threadIdx.x;
    int b_base = blockIdx.y * 64;

    for (int p = tid; p < 48 * 64; p += 256) {
        int j = p >> 6, bl = p & 63;
        int which = j >> 4;
        int b = b_base + bl;
        int id = (which == 0) ? ig[b] : (which == 1) ? ish[b] : ic[b];
        As[j][bl] = table[(size_t)id * DIM + (j & 15)];
    }
    __syncthreads();

    int tx = tid & 31, ty = tid >> 5;
    int col = blockIdx.x * 32 + tx;
    if (col >= ECOLS) return;
    int b0 = ty * 8;

    float acc[8];
#pragma unroll
    for (int r = 0; r < 8; r++) acc[r] = 0.f;

    int ii, kk;
    if (col < 1728) {
        ii = col / 36; kk = col - ii * 36;
        const float* wp = W1 + (size_t)(144 + ii * 48) * 36 + kk;
#pragma unroll 4
        for (int j = 0; j < 48; j++) {
            float w = wp[j * 36];
            float4 a0 = *(const float4*)&As[j][b0];
            float4 a1 = *(const float4*)&As[j][b0 + 4];
            acc[0] += w * a0.x; acc[1] += w * a0.y; acc[2] += w * a0.z; acc[3] += w * a0.w;
            acc[4] += w * a1.x; acc[5] += w * a1.y; acc[6] += w * a1.z; acc[7] += w * a1.w;
        }
        float wcb = W1[(96 + ii) * 36 + kk] - W1[(48 + ii) * 36 + kk];
#pragma unroll
        for (int r = 0; r < 8; r++) acc[r] += wcb;
    } else {
        ii = 48; kk = col - 1728;
#pragma unroll 4
        for (int j = 0; j < 48; j++) {
            float w = W1[j * 36 + kk] + W1[(48 + j) * 36 + kk];
            float4 a0 = *(const float4*)&As[j][b0];
            float4 a1 = *(const float4*)&As[j][b0 + 4];
            acc[0] += w * a0.x; acc[1] += w * a0.y; acc[2] += w * a0.z; acc[3] += w * a0.w;
            acc[4] += w * a1.x; acc[5] += w * a1.y; acc[6] += w * a1.z; acc[7] += w * a1.w;
        }
        float bb = b1[kk];
#pragma unroll
        for (int r = 0; r < 8; r++) acc[r] += bb;
    }
    int kq = kk >> 2, c = kk & 3;
    size_t base = (size_t)(ii * 9 + kq) * 2048 + c;
#pragma unroll
    for (int r = 0; r < 8; r++)
        g_Ec[base + (size_t)(b_base + b0 + r) * 4] = acc[r];
}

// ============================================================================
// KB1: h_pre for KEPT s. grid (100, 4), block 128 (thread = one b).
// ============================================================================
__global__ __launch_bounds__(128) void kB1_h(
        const float* __restrict__ table,
        const int* __restrict__ vg, const int* __restrict__ vsh,
        const int* __restrict__ vc) {
    int s = blockIdx.x;
    if (!g_skeep[s]) return;
    int b = blockIdx.y * 128 + threadIdx.x;

    int id0 = vg[b * SEQ + s];
    int id1 = vsh[b * SEQ + s];
    int id2 = vc[b * SEQ + s];

    float vs[48];
    {
        const float4* r = (const float4*)(table + (size_t)id0 * DIM);
        float4 a = r[0], bb = r[1], cc = r[2], dd = r[3];
        vs[0]=a.x; vs[1]=a.y; vs[2]=a.z; vs[3]=a.w;
        vs[4]=bb.x; vs[5]=bb.y; vs[6]=bb.z; vs[7]=bb.w;
        vs[8]=cc.x; vs[9]=cc.y; vs[10]=cc.z; vs[11]=cc.w;
        vs[12]=dd.x; vs[13]=dd.y; vs[14]=dd.z; vs[15]=dd.w;
        r = (const float4*)(table + (size_t)id1 * DIM);
        a = r[0]; bb = r[1]; cc = r[2]; dd = r[3];
        vs[16]=a.x; vs[17]=a.y; vs[18]=a.z; vs[19]=a.w;
        vs[20]=bb.x; vs[21]=bb.y; vs[22]=bb.z; vs[23]=bb.w;
        vs[24]=cc.x; vs[25]=cc.y; vs[26]=cc.z; vs[27]=cc.w;
        vs[28]=dd.x; vs[29]=dd.y; vs[30]=dd.z; vs[31]=dd.w;
        r = (const float4*)(table + (size_t)id2 * DIM);
        a = r[0]; bb = r[1]; cc = r[2]; dd = r[3];
        vs[32]=a.x; vs[33]=a.y; vs[34]=a.z; vs[35]=a.w;
        vs[36]=bb.x; vs[37]=bb.y; vs[38]=bb.z; vs[39]=bb.w;
        vs[40]=cc.x; vs[41]=cc.y; vs[42]=cc.z; vs[43]=cc.w;
        vs[44]=dd.x; vs[45]=dd.y; vs[46]=dd.z; vs[47]=dd.w;
    }

    const float4* E4 = (const float4*)g_Ec;
    float h[36];
#pragma unroll
    for (int kq = 0; kq < 9; kq++) {
        float4 cv = E4[(size_t)(432 + kq) * 512 + b];
        h[kq*4+0]=cv.x; h[kq*4+1]=cv.y; h[kq*4+2]=cv.z; h[kq*4+3]=cv.w;
    }
    for (int i = 0; i < 48; i++) {
        float v = vs[i];
#pragma unroll
        for (int kq = 0; kq < 9; kq++) {
            float4 e = E4[(size_t)(i * 9 + kq) * 512 + b];
            h[kq*4+0] += v * e.x; h[kq*4+1] += v * e.y;
            h[kq*4+2] += v * e.z; h[kq*4+3] += v * e.w;
        }
    }
#pragma unroll
    for (int k = 0; k < 36; k++)
        g_h[(size_t)(s * NH + k) * BSZ + b] = h[k];
}

// ============================================================================
// KB2: batch stats (redundant per block) + dice + score + mask -> coef.
// grid (100, 16): 32 b per block; block 128 = 32 b x 4 k-quarters.
// ============================================================================
__global__ void kB2_coef(const int* __restrict__ vg,
                         const float* __restrict__ alpha,
                         const float* __restrict__ wout,
                         const float* __restrict__ bout) {
    int s = blockIdx.x;
    if (!g_skeep[s]) return;
    __shared__ float muS[NH], isS[NH];
    int t = threadIdx.x;
    int w = t >> 5, lane = t & 31;

    // stats over all 512 b for this block's 9 k-rows per warp
    for (int r = 0; r < 9; r++) {
        int k = w * 9 + r;
        const float4* row = (const float4*)(g_h + (size_t)(s * NH + k) * BSZ);
        float sm = 0.f, sq = 0.f;
#pragma unroll
        for (int i = 0; i < 4; i++) {
            float4 v = row[lane + 32 * i];
            sm += v.x + v.y + v.z + v.w;
            sq += v.x * v.x + v.y * v.y + v.z * v.z + v.w * v.w;
        }
#pragma unroll
        for (int o = 16; o; o >>= 1) {
            sm += __shfl_down_sync(0xffffffffu, sm, o);
            sq += __shfl_down_sync(0xffffffffu, sq, o);
        }
        if (lane == 0) {
            float mu = sm * (1.f / 512.f);
            float var = sq * (1.f / 512.f) - mu * mu;
            muS[k] = mu; isS[k] = rsqrtf(var + 1e-3f);
        }
    }
    __syncthreads();

    int bl = t >> 2, quarter = t & 3;
    int b = blockIdx.y * 32 + bl;
    float acc = 0.f;
#pragma unroll
    for (int kk = 0; kk < 9; kk++) {
        int k = quarter * 9 + kk;
        float x = g_h[(size_t)(s * NH + k) * BSZ + b];
        float xn = (x - muS[k]) * isS[k];
        float p = sigm(xn);
        acc += wout[k] * x * (p + alpha[k] * (1.f - p));
    }
    acc += __shfl_xor_sync(0xffffffffu, acc, 1);
    acc += __shfl_xor_sync(0xffffffffu, acc, 2);
    if (quarter == 0) {
        int vgv = vg[b * SEQ + s];
        g_coef[s * BSZ + b] = (vgv == 0) ? (acc + bout[0]) : 0.f;
    }
}

// ============================================================================
// K5: x build (profile + x_inter) + MLP1 (smem-tiled W) + LN -> y1T.
// grid 128 (4 b each), block 256.
// ============================================================================
__global__ void k5_mlp1(const float* __restrict__ table, IdPtrs ids,
                        const int* __restrict__ vg, const int* __restrict__ vsh,
                        const int* __restrict__ vc,
                        const float* __restrict__ W, const float* __restrict__ bias,
                        const float* __restrict__ gln, const float* __restrict__ beta) {
    __shared__ float xs[4][COMB];
    __shared__ float Ws[16][200];
    __shared__ float ys[4][201];
    __shared__ float muS[4], isS[4];
    __shared__ int skeepS[SEQ];
    __shared__ int anyS;
    __shared__ float csh[4];
    int t = threadIdx.x;
    int b0 = blockIdx.x * 4;

    if (t == 0) anyS = g_any;
    if (t < SEQ) skeepS[t] = g_skeep[t];
    for (int p = t; p < 4 * 128; p += 256) {
        int bl = p >> 7, f = p & 127;
        xs[bl][f] = table[(size_t)ids.p[f >> 4][b0 + bl] * DIM + (f & 15)];
    }
    if (t < 4 * 48) { int bl = t / 48, i = t - bl * 48; xs[bl][128 + i] = 0.f; }
    __syncthreads();

    if (anyS) {
        for (int s = 0; s < SEQ; s++) {
            if (!skeepS[s]) continue;
            if (t < 4) csh[t] = g_coef[s * BSZ + b0 + t];
            __syncthreads();
            if (t < 4 * 48) {
                int bl = t / 48, i = t - bl * 48;
                float c = csh[bl];
                if (c != 0.f) {
                    int which = i >> 4;
                    int id = (which == 0) ? vg[(b0 + bl) * SEQ + s]
                           : (which == 1) ? vsh[(b0 + bl) * SEQ + s]
                                          : vc[(b0 + bl) * SEQ + s];
                    xs[bl][128 + i] += c * table[(size_t)id * DIM + (i & 15)];
                }
            }
            __syncthreads();
        }
    }

    float acc[4];
    {
        float bb = (t < 200) ? bias[t] : 0.f;
        acc[0] = acc[1] = acc[2] = acc[3] = bb;
    }
    for (int j0 = 0; j0 < COMB; j0 += 16) {
        const float4* src = (const float4*)(W + j0 * 200);
        for (int p = t; p < 800; p += 256) {
            int row = p / 50, c4 = p - row * 50;
            *(float4*)&Ws[row][c4 * 4] = src[row * 50 + c4];
        }
        __syncthreads();
        if (t < 200) {
#pragma unroll
            for (int jj = 0; jj < 16; jj++) {
                float w = Ws[jj][t];
                acc[0] += w * xs[0][j0 + jj];
                acc[1] += w * xs[1][j0 + jj];
                acc[2] += w * xs[2][j0 + jj];
                acc[3] += w * xs[3][j0 + jj];
            }
        }
        __syncthreads();
    }
    if (t < 200) {
#pragma unroll
        for (int r = 0; r < 4; r++) ys[r][t] = acc[r];
    }
    __syncthreads();
    if (t < 128) {
        int w = t >> 5, lane = t & 31;
        float sm = 0.f, sq = 0.f;
        for (int c = lane; c < 200; c += 32) { float v = ys[w][c]; sm += v; sq += v * v; }
#pragma unroll
        for (int o = 16; o; o >>= 1) {
            sm += __shfl_down_sync(0xffffffffu, sm, o);
            sq += __shfl_down_sync(0xffffffffu, sq, o);
        }
        if (lane == 0) {
            float mu = sm * (1.f / 200.f);
            float var = sq * (1.f / 200.f) - mu * mu;
            muS[w] = mu; isS[w] = rsqrtf(var + 1e-3f);
        }
    }
    __syncthreads();
    if (t < 200) {
        float gg = gln[t], be = beta[t];
#pragma unroll
        for (int r = 0; r < 4; r++)
            g_y1[(size_t)t * BSZ + b0 + r] = (ys[r][t] - muS[r]) * isS[r] * gg + be;
    }
}

// ============================================================================
// S1: per-feature batch stats of y1 + dice -> d1. grid 200, block 256.
// ============================================================================
__global__ void kS1_dice(const float* __restrict__ alpha1) {
    __shared__ float red[16];
    __shared__ float muB, isB;
    int f = blockIdx.x, t = threadIdx.x;
    int w = t >> 5, lane = t & 31;
    const float2* row = (const float2*)(g_y1 + (size_t)f * BSZ);
    float2 v = row[t];
    float sm = v.x + v.y, sq = v.x * v.x + v.y * v.y;
#pragma unroll
    for (int o = 16; o; o >>= 1) {
        sm += __shfl_down_sync(0xffffffffu, sm, o);
        sq += __shfl_down_sync(0xffffffffu, sq, o);
    }
    if (lane == 0) { red[w] = sm; red[8 + w] = sq; }
    __syncthreads();
    if (t == 0) {
        float s = 0.f, q = 0.f;
        for (int j = 0; j < 8; j++) { s += red[j]; q += red[8 + j]; }
        float mu = s * (1.f / 512.f);
        float var = q * (1.f / 512.f) - mu * mu;
        muB = mu; isB = rsqrtf(var + 1e-3f);
    }
    __syncthreads();
    float a = alpha1[f];
    float mu = muB, is = isB;
    float p0 = sigm((v.x - mu) * is);
    float p1 = sigm((v.y - mu) * is);
    float2 d;
    d.x = v.x * (p0 + a * (1.f - p0));
    d.y = v.y * (p1 + a * (1.f - p1));
    ((float2*)(g_d1 + (size_t)f * BSZ))[t] = d;
}

// ============================================================================
// K7: MLP2 (smem-tiled W2) + LN -> y2T. grid 32 (16 b each), block 256.
// ============================================================================
__global__ void k7_mlp2(const float* __restrict__ W2, const float* __restrict__ b2,
                        const float* __restrict__ g2, const float* __restrict__ be2) {
    __shared__ float d1s[200][17];
    __shared__ float Ws2[20][80];
    __shared__ float ys[80][17];
    __shared__ float muS[16], isS[16];
    int t = threadIdx.x;
    int b0 = blockIdx.x * 16;

    for (int p = t; p < 800; p += 256) {
        int f = p >> 2, c = p & 3;
        float4 v = *(const float4*)(g_d1 + (size_t)f * BSZ + b0 + c * 4);
        d1s[f][c * 4 + 0] = v.x; d1s[f][c * 4 + 1] = v.y;
        d1s[f][c * 4 + 2] = v.z; d1s[f][c * 4 + 3] = v.w;
    }

    float acc[8];
    {
        float bb = (t < 160) ? b2[t % 80] : 0.f;
#pragma unroll
        for (int r = 0; r < 8; r++) acc[r] = bb;
    }
    for (int j0 = 0; j0 < 200; j0 += 20) {
        __syncthreads();
        for (int p = t; p < 400; p += 256) {
            int row = p / 20, c4 = p - row * 20;
            *(float4*)&Ws2[row][c4 * 4] = *(const float4*)(W2 + (j0 + row) * 80 + c4 * 4);
        }
        __syncthreads();
        if (t < 160) {
            int f = t % 80, grp = t / 80;
#pragma unroll
            for (int jj = 0; jj < 20; jj++) {
                float w = Ws2[jj][f];
#pragma unroll
                for (int r = 0; r < 8; r++) acc[r] += w * d1s[j0 + jj][grp * 8 + r];
            }
        }
    }
    __syncthreads();
    if (t < 160) {
        int f = t % 80, grp = t / 80;
#pragma unroll
        for (int r = 0; r < 8; r++) ys[f][grp * 8 + r] = acc[r];
    }
    __syncthreads();
    {
        int w = t >> 5, lane = t & 31;
#pragma unroll
        for (int rep = 0; rep < 2; rep++) {
            int bl = w + rep * 8;
            float sm = 0.f, sq = 0.f;
            for (int c = lane; c < 80; c += 32) { float v = ys[c][bl]; sm += v; sq += v * v; }
#pragma unroll
            for (int o = 16; o; o >>= 1) {
                sm += __shfl_down_sync(0xffffffffu, sm, o);
                sq += __shfl_down_sync(0xffffffffu, sq, o);
            }
            if (lane == 0) {
                float mu = sm * (1.f / 80.f);
                float var = sq * (1.f / 80.f) - mu * mu;
                muS[bl] = mu; isS[bl] = rsqrtf(var + 1e-3f);
            }
        }
    }
    __syncthreads();
    if (t < 160) {
        int f = t % 80, grp = t / 80;
        float gg = g2[f], be = be2[f];
#pragma unroll
        for (int r = 0; r < 8; r++) {
            int bl = grp * 8 + r;
            g_y2[(size_t)f * BSZ + b0 + bl] = (ys[f][bl] - muS[bl]) * isS[bl] * gg + be;
        }
    }
}

// ============================================================================
// K9: redundant stats2 + dice + out GEMM + softmax. grid 32 (16 b), block 256.
// ============================================================================
__global__ void k9_out(const float* __restrict__ alpha2, const float* __restrict__ W,
                       const float* __restrict__ bout, float* __restrict__ out) {
    __shared__ float mu2[80], is2[80];
    __shared__ float Wsh[160];
    __shared__ float Ash[80];
    int t = threadIdx.x;
    int w = t >> 5, lane = t & 31;
    int b0 = blockIdx.x * 16;

    if (t < 160) Wsh[t] = W[t];
    if (t < 80) Ash[t] = alpha2[t];
    for (int r = 0; r < 10; r++) {
        int f = w * 10 + r;
        const float4* row = (const float4*)(g_y2 + (size_t)f * BSZ);
        float sm = 0.f, sq = 0.f;
#pragma unroll
        for (int i = 0; i < 4; i++) {
            float4 v = row[lane + 32 * i];
            sm += v.x + v.y + v.z + v.w;
            sq += v.x * v.x + v.y * v.y + v.z * v.z + v.w * v.w;
        }
#pragma unroll
        for (int o = 16; o; o >>= 1) {
            sm += __shfl_down_sync(0xffffffffu, sm, o);
            sq += __shfl_down_sync(0xffffffffu, sq, o);
        }
        if (lane == 0) {
            float mu = sm * (1.f / 512.f);
            float var = sq * (1.f / 512.f) - mu * mu;
            mu2[f] = mu; is2[f] = rsqrtf(var + 1e-3f);
        }
    }
    __syncthreads();

    float bo0 = bout[0], bo1 = bout[1];
#pragma unroll
    for (int rep = 0; rep < 2; rep++) {
        int b = b0 + w + rep * 8;
        float a0 = 0.f, a1 = 0.f;
        for (int f = lane; f < 80; f += 32) {
            float v = g_y2[(size_t)f * BSZ + b];
            float xn = (v - mu2[f]) * is2[f];
            float p = sigm(xn);
            float h = v * (p + Ash[f] * (1.f - p));
            a0 += h * Wsh[2 * f];
            a1 += h * Wsh[2 * f + 1];
        }
#pragma unroll
        for (int o = 16; o; o >>= 1) {
            a0 += __shfl_down_sync(0xffffffffu, a0, o);
            a1 += __shfl_down_sync(0xffffffffu, a1, o);
        }
        if (lane == 0) {
            a0 += bo0; a1 += bo1;
            float m = fmaxf(a0, a1);
            float e0 = __expf(a0 - m), e1 = __expf(a1 - m);
            float inv = __fdividef(1.f, e0 + e1);
            out[b * 2] = e0 * inv;
            out[b * 2 + 1] = e1 * inv;
        }
    }
}

// ============================================================================
extern "C" void kernel_launch(void* const* d_in, const int* in_sizes, int n_in,
                              void* d_out, int out_size) {
    (void)in_sizes; (void)n_in; (void)out_size;
    const int* uid  = (const int*)d_in[0];
    const int* ut1  = (const int*)d_in[1];
    const int* ut2  = (const int*)d_in[2];
    const int* ut3  = (const int*)d_in[3];
    const int* ut4  = (const int*)d_in[4];
    const int* ig   = (const int*)d_in[5];
    const int* ish  = (const int*)d_in[6];
    const int* ic   = (const int*)d_in[7];
    const int* vg   = (const int*)d_in[8];
    const int* vsh  = (const int*)d_in[9];
    const int* vc   = (const int*)d_in[10];
    const float* table     = (const float*)d_in[11];
    const float* W_act1    = (const float*)d_in[12];
    const float* b_act1    = (const float*)d_in[13];
    const float* alpha_act = (const float*)d_in[14];
    const float* W_act_out = (const float*)d_in[15];
    const float* b_act_out = (const float*)d_in[16];
    const float* W_mlp1    = (const float*)d_in[17];
    const float* b_mlp1    = (const float*)d_in[18];
    const float* g_ln1     = (const float*)d_in[19];
    const float* beta_ln1  = (const float*)d_in[20];
    const float* alpha_m1  = (const float*)d_in[21];
    const float* W_mlp2    = (const float*)d_in[22];
    const float* b_mlp2    = (const float*)d_in[23];
    const float* g_ln2     = (const float*)d_in[24];
    const float* beta_ln2  = (const float*)d_in[25];
    const float* alpha_m2  = (const float*)d_in[26];
    const float* W_out     = (const float*)d_in[27];
    const float* b_out     = (const float*)d_in[28];
    float* out = (float*)d_out;

    IdPtrs ids;
    ids.p[0] = uid; ids.p[1] = ut1; ids.p[2] = ut2; ids.p[3] = ut3;
    ids.p[4] = ut4; ids.p[5] = ig;  ids.p[6] = ish; ids.p[7] = ic;

    kA_mask<<<1, 1024>>>(vg);
    k1_EC<<<dim3(56, 8), 256>>>(table, ig, ish, ic, W_act1, b_act1);
    kB1_h<<<dim3(SEQ, 4), 128>>>(table, vg, vsh, vc);
    kB2_coef<<<dim3(SEQ, 16), 128>>>(vg, alpha_act, W_act_out, b_act_out);
    k5_mlp1<<<128, 256>>>(table, ids, vg, vsh, vc, W_mlp1, b_mlp1, g_ln1, beta_ln1);
    kS1_dice<<<200, 256>>>(alpha_m1);
    k7_mlp2<<<32, 256>>>(W_mlp2, b_mlp2, g_ln2, beta_ln2);
    k9_out<<<32, 256>>>(alpha_m2, W_out, b_out, out);
}

// round 6
// speedup vs baseline: 2.5206x; 1.0006x over previous
#include <cuda_runtime.h>
#include <math.h>

#define BSZ   512
#define SEQ   100
#define DIM   16
#define NH    36
#define ECOLS 1764        // 48*36 (E) + 36 (c)
#define COMB  176
#define NBLK  128
#define NTHR  256

// -------- scratch (__device__ globals: allocation-free) --------
__device__ __align__(16) float g_Ec[BSZ * ECOLS];      // [(i*9+kq)*2048 + b*4 + c]
__device__ __align__(16) float g_h[SEQ * NH * BSZ];    // [(s*36+k)*512 + b]
__device__ __align__(16) float g_coef[SEQ * BSZ];      // [s][b]
__device__ __align__(16) float g_y1[200 * BSZ];        // [f][b]
__device__ __align__(16) float g_d1[200 * BSZ];        // dice(y1) [f][b]
__device__ __align__(16) float g_y2[80 * BSZ];         // [f][b]
__device__ int g_skeep[SEQ];
__device__ unsigned g_cnt;                              // barrier arrive count
__device__ volatile unsigned g_gen;                     // barrier generation

struct IdPtrs { const int* p[8]; };

union SMem {
    struct { float As[48][64]; } p2;                                   // 12 KB
    struct { float mu[NH]; float is[NH]; } p3;
    struct { float xs[4][COMB]; float Ws[16][200]; float ys[4][201];
             float mu[4]; float is[4]; float csh[4]; } p4;             // ~19 KB
    struct { float red[16]; float mu; float is; } p5;
    struct { float d1s[200][17]; float Ws2[20][80]; float ys[80][17];
             float mu[16]; float is[16]; } p6;                         // ~25.6 KB
    struct { float mu[80]; float is[80]; float Wsh[160]; float Ash[80]; } p7;
};

__device__ __forceinline__ float sigm(float x) {
    return __fdividef(1.f, 1.f + __expf(-x));
}

// software grid barrier: safe because all NBLK blocks are co-resident
// (NBLK=128 <= 148 SMs, <=255 regs/thr, static smem < 48KB)
__device__ __forceinline__ void gbar() {
    __syncthreads();
    if (threadIdx.x == 0) {
        unsigned gen = g_gen;
        __threadfence();
        if (atomicAdd(&g_cnt, 1u) == NBLK - 1) {
            g_cnt = 0;
            __threadfence();
            g_gen = gen + 1;
        } else {
            while (g_gen == gen) __nanosleep(64);
        }
    }
    __syncthreads();
}

__global__ __launch_bounds__(NTHR) void din_fused(
        const float* __restrict__ table, IdPtrs ids,
        const int* __restrict__ vg, const int* __restrict__ vsh,
        const int* __restrict__ vc,
        const float* __restrict__ W1, const float* __restrict__ b1,
        const float* __restrict__ alpha_a, const float* __restrict__ wout,
        const float* __restrict__ bout,
        const float* __restrict__ Wm1, const float* __restrict__ bm1,
        const float* __restrict__ gl1, const float* __restrict__ bl1,
        const float* __restrict__ al1,
        const float* __restrict__ Wm2, const float* __restrict__ bm2,
        const float* __restrict__ gl2, const float* __restrict__ bl2,
        const float* __restrict__ al2,
        const float* __restrict__ Wo, const float* __restrict__ bo,
        float* __restrict__ out) {
    __shared__ SMem sm;
    __shared__ int skeepS[SEQ];
    int bid = blockIdx.x;
    int t = threadIdx.x;

    // ---------------- P1: per-s keep mask ----------------
    if (bid < SEQ) {
        int any = 0;
        for (int b = t; b < BSZ; b += NTHR) any |= (vg[b * SEQ + bid] == 0);
        int r = __syncthreads_or(any);
        if (t == 0) g_skeep[bid] = r;
    }
    gbar();

    // every block: cache skeep + compute anyAll
    int anyL = 0;
    for (int i = t; i < SEQ; i += NTHR) { int v = g_skeep[i]; skeepS[i] = v; anyL |= v; }
    int anyAll = __syncthreads_or(anyL);

    // ---------------- P2: E GEMM (only if any kept) ----------------
    if (anyAll) {
        for (int tile = bid; tile < 448; tile += NBLK) {
            int cx = tile % 56, by = tile / 56;
            int b_base = by * 64;
            for (int p = t; p < 48 * 64; p += NTHR) {
                int j = p >> 6, bl = p & 63;
                int which = j >> 4;
                int b = b_base + bl;
                int id = ids.p[5 + which][b];   // i_goods, i_shop, i_cate
                sm.p2.As[j][bl] = table[(size_t)id * DIM + (j & 15)];
            }
            __syncthreads();
            int tx = t & 31, ty = t >> 5;
            int col = cx * 32 + tx;
            if (col < ECOLS) {
                int b0 = ty * 8;
                float acc[8];
#pragma unroll
                for (int r = 0; r < 8; r++) acc[r] = 0.f;
                int ii, kk;
                if (col < 1728) {
                    ii = col / 36; kk = col - ii * 36;
                    const float* wp = W1 + (size_t)(144 + ii * 48) * 36 + kk;
#pragma unroll 4
                    for (int j = 0; j < 48; j++) {
                        float w = wp[j * 36];
                        float4 a0 = *(const float4*)&sm.p2.As[j][b0];
                        float4 a1 = *(const float4*)&sm.p2.As[j][b0 + 4];
                        acc[0] += w * a0.x; acc[1] += w * a0.y; acc[2] += w * a0.z; acc[3] += w * a0.w;
                        acc[4] += w * a1.x; acc[5] += w * a1.y; acc[6] += w * a1.z; acc[7] += w * a1.w;
                    }
                    float wcb = W1[(96 + ii) * 36 + kk] - W1[(48 + ii) * 36 + kk];
#pragma unroll
                    for (int r = 0; r < 8; r++) acc[r] += wcb;
                } else {
                    ii = 48; kk = col - 1728;
#pragma unroll 4
                    for (int j = 0; j < 48; j++) {
                        float w = W1[j * 36 + kk] + W1[(48 + j) * 36 + kk];
                        float4 a0 = *(const float4*)&sm.p2.As[j][b0];
                        float4 a1 = *(const float4*)&sm.p2.As[j][b0 + 4];
                        acc[0] += w * a0.x; acc[1] += w * a0.y; acc[2] += w * a0.z; acc[3] += w * a0.w;
                        acc[4] += w * a1.x; acc[5] += w * a1.y; acc[6] += w * a1.z; acc[7] += w * a1.w;
                    }
                    float bb = b1[kk];
#pragma unroll
                    for (int r = 0; r < 8; r++) acc[r] += bb;
                }
                int kq = kk >> 2, c = kk & 3;
                size_t base = (size_t)(ii * 9 + kq) * 2048 + c;
#pragma unroll
                for (int r = 0; r < 8; r++)
                    g_Ec[base + (size_t)(b_base + b0 + r) * 4] = acc[r];
            }
            __syncthreads();
        }
    }
    gbar();

    // ---------------- P3a: h_pre for kept s ----------------
    if (anyAll) {
        for (int it = bid; it < 200; it += NBLK) {
            int s = it >> 1, half = it & 1;
            if (!skeepS[s]) continue;
            int b = half * 256 + t;
            int id0 = vg[b * SEQ + s];
            int id1 = vsh[b * SEQ + s];
            int id2 = vc[b * SEQ + s];
            float vs[48];
            {
                const float4* r = (const float4*)(table + (size_t)id0 * DIM);
                float4 a = r[0], bb = r[1], cc = r[2], dd = r[3];
                vs[0]=a.x; vs[1]=a.y; vs[2]=a.z; vs[3]=a.w;
                vs[4]=bb.x; vs[5]=bb.y; vs[6]=bb.z; vs[7]=bb.w;
                vs[8]=cc.x; vs[9]=cc.y; vs[10]=cc.z; vs[11]=cc.w;
                vs[12]=dd.x; vs[13]=dd.y; vs[14]=dd.z; vs[15]=dd.w;
                r = (const float4*)(table + (size_t)id1 * DIM);
                a = r[0]; bb = r[1]; cc = r[2]; dd = r[3];
                vs[16]=a.x; vs[17]=a.y; vs[18]=a.z; vs[19]=a.w;
                vs[20]=bb.x; vs[21]=bb.y; vs[22]=bb.z; vs[23]=bb.w;
                vs[24]=cc.x; vs[25]=cc.y; vs[26]=cc.z; vs[27]=cc.w;
                vs[28]=dd.x; vs[29]=dd.y; vs[30]=dd.z; vs[31]=dd.w;
                r = (const float4*)(table + (size_t)id2 * DIM);
                a = r[0]; bb = r[1]; cc = r[2]; dd = r[3];
                vs[32]=a.x; vs[33]=a.y; vs[34]=a.z; vs[35]=a.w;
                vs[36]=bb.x; vs[37]=bb.y; vs[38]=bb.z; vs[39]=bb.w;
                vs[40]=cc.x; vs[41]=cc.y; vs[42]=cc.z; vs[43]=cc.w;
                vs[44]=dd.x; vs[45]=dd.y; vs[46]=dd.z; vs[47]=dd.w;
            }
            const float4* E4 = (const float4*)g_Ec;
            float h[36];
#pragma unroll
            for (int kq = 0; kq < 9; kq++) {
                float4 cv = E4[(size_t)(432 + kq) * 512 + b];
                h[kq*4+0]=cv.x; h[kq*4+1]=cv.y; h[kq*4+2]=cv.z; h[kq*4+3]=cv.w;
            }
            for (int i = 0; i < 48; i++) {
                float v = vs[i];
#pragma unroll
                for (int kq = 0; kq < 9; kq++) {
                    float4 e = E4[(size_t)(i * 9 + kq) * 512 + b];
                    h[kq*4+0] += v * e.x; h[kq*4+1] += v * e.y;
                    h[kq*4+2] += v * e.z; h[kq*4+3] += v * e.w;
                }
            }
#pragma unroll
            for (int k = 0; k < 36; k++)
                g_h[(size_t)(s * NH + k) * BSZ + b] = h[k];
        }
    }
    gbar();

    // ---------------- P3b: stats + dice + score + mask -> coef ----------------
    if (anyAll) {
        float bout0 = bout[0];
        for (int it = bid; it < 200; it += NBLK) {
            int s = it >> 1, half = it & 1;
            if (!skeepS[s]) continue;
            int w = t >> 5, lane = t & 31;
            for (int k = w; k < NH; k += 8) {
                const float4* row = (const float4*)(g_h + (size_t)(s * NH + k) * BSZ);
                float smv = 0.f, sq = 0.f;
#pragma unroll
                for (int i = 0; i < 4; i++) {
                    float4 v = row[lane + 32 * i];
                    smv += v.x + v.y + v.z + v.w;
                    sq += v.x * v.x + v.y * v.y + v.z * v.z + v.w * v.w;
                }
#pragma unroll
                for (int o = 16; o; o >>= 1) {
                    smv += __shfl_down_sync(0xffffffffu, smv, o);
                    sq  += __shfl_down_sync(0xffffffffu, sq, o);
                }
                if (lane == 0) {
                    float mu = smv * (1.f / 512.f);
                    float var = sq * (1.f / 512.f) - mu * mu;
                    sm.p3.mu[k] = mu; sm.p3.is[k] = rsqrtf(var + 1e-3f);
                }
            }
            __syncthreads();
            int b = half * 256 + t;
            float accv = 0.f;
#pragma unroll 4
            for (int k = 0; k < NH; k++) {
                float x = g_h[(size_t)(s * NH + k) * BSZ + b];
                float xn = (x - sm.p3.mu[k]) * sm.p3.is[k];
                float p = sigm(xn);
                accv += wout[k] * x * (p + alpha_a[k] * (1.f - p));
            }
            int vgv = vg[b * SEQ + s];
            g_coef[s * BSZ + b] = (vgv == 0) ? (accv + bout0) : 0.f;
            __syncthreads();
        }
    }
    gbar();

    // ---------------- P4: x build + MLP1 + LN -> y1T (one 4-b item per block) --
    {
        int b0 = bid * 4;
        for (int p = t; p < 4 * 128; p += NTHR) {
            int bl = p >> 7, f = p & 127;
            sm.p4.xs[bl][f] = table[(size_t)ids.p[f >> 4][b0 + bl] * DIM + (f & 15)];
        }
        if (t < 4 * 48) { int bl = t / 48, i = t - bl * 48; sm.p4.xs[bl][128 + i] = 0.f; }
        __syncthreads();

        if (anyAll) {
            for (int s = 0; s < SEQ; s++) {
                if (!skeepS[s]) continue;
                if (t < 4) sm.p4.csh[t] = g_coef[s * BSZ + b0 + t];
                __syncthreads();
                if (t < 4 * 48) {
                    int bl = t / 48, i = t - bl * 48;
                    float c = sm.p4.csh[bl];
                    if (c != 0.f) {
                        int which = i >> 4;
                        int id = (which == 0) ? vg[(b0 + bl) * SEQ + s]
                               : (which == 1) ? vsh[(b0 + bl) * SEQ + s]
                                              : vc[(b0 + bl) * SEQ + s];
                        sm.p4.xs[bl][128 + i] += c * table[(size_t)id * DIM + (i & 15)];
                    }
                }
                __syncthreads();
            }
        }

        float acc[4];
        {
            float bb = (t < 200) ? bm1[t] : 0.f;
            acc[0] = acc[1] = acc[2] = acc[3] = bb;
        }
        for (int j0 = 0; j0 < COMB; j0 += 16) {
            const float4* src = (const float4*)(Wm1 + j0 * 200);
            for (int p = t; p < 800; p += NTHR) {
                int row = p / 50, c4 = p - row * 50;
                *(float4*)&sm.p4.Ws[row][c4 * 4] = src[row * 50 + c4];
            }
            __syncthreads();
            if (t < 200) {
#pragma unroll
                for (int jj = 0; jj < 16; jj++) {
                    float w = sm.p4.Ws[jj][t];
                    acc[0] += w * sm.p4.xs[0][j0 + jj];
                    acc[1] += w * sm.p4.xs[1][j0 + jj];
                    acc[2] += w * sm.p4.xs[2][j0 + jj];
                    acc[3] += w * sm.p4.xs[3][j0 + jj];
                }
            }
            __syncthreads();
        }
        if (t < 200) {
#pragma unroll
            for (int r = 0; r < 4; r++) sm.p4.ys[r][t] = acc[r];
        }
        __syncthreads();
        if (t < 128) {
            int w = t >> 5, lane = t & 31;
            float smv = 0.f, sq = 0.f;
            for (int c = lane; c < 200; c += 32) { float v = sm.p4.ys[w][c]; smv += v; sq += v * v; }
#pragma unroll
            for (int o = 16; o; o >>= 1) {
                smv += __shfl_down_sync(0xffffffffu, smv, o);
                sq  += __shfl_down_sync(0xffffffffu, sq, o);
            }
            if (lane == 0) {
                float mu = smv * (1.f / 200.f);
                float var = sq * (1.f / 200.f) - mu * mu;
                sm.p4.mu[w] = mu; sm.p4.is[w] = rsqrtf(var + 1e-3f);
            }
        }
        __syncthreads();
        if (t < 200) {
            float gg = gl1[t], be = bl1[t];
#pragma unroll
            for (int r = 0; r < 4; r++)
                g_y1[(size_t)t * BSZ + b0 + r] = (acc[r] - sm.p4.mu[r]) * sm.p4.is[r] * gg + be;
        }
    }
    gbar();

    // ---------------- P5: batch stats of y1 + dice -> d1 ----------------
    for (int f = bid; f < 200; f += NBLK) {
        int w = t >> 5, lane = t & 31;
        const float2* row = (const float2*)(g_y1 + (size_t)f * BSZ);
        float2 v = row[t];
        float smv = v.x + v.y, sq = v.x * v.x + v.y * v.y;
#pragma unroll
        for (int o = 16; o; o >>= 1) {
            smv += __shfl_down_sync(0xffffffffu, smv, o);
            sq  += __shfl_down_sync(0xffffffffu, sq, o);
        }
        if (lane == 0) { sm.p5.red[w] = smv; sm.p5.red[8 + w] = sq; }
        __syncthreads();
        if (t == 0) {
            float s2 = 0.f, q2 = 0.f;
            for (int j = 0; j < 8; j++) { s2 += sm.p5.red[j]; q2 += sm.p5.red[8 + j]; }
            float mu = s2 * (1.f / 512.f);
            float var = q2 * (1.f / 512.f) - mu * mu;
            sm.p5.mu = mu; sm.p5.is = rsqrtf(var + 1e-3f);
        }
        __syncthreads();
        float a = al1[f];
        float mu = sm.p5.mu, is = sm.p5.is;
        float p0 = sigm((v.x - mu) * is);
        float p1 = sigm((v.y - mu) * is);
        float2 d;
        d.x = v.x * (p0 + a * (1.f - p0));
        d.y = v.y * (p1 + a * (1.f - p1));
        ((float2*)(g_d1 + (size_t)f * BSZ))[t] = d;
        __syncthreads();
    }
    gbar();

    // ---------------- P6: MLP2 + LN -> y2T ----------------
    if (bid < 32) {
        int b0 = bid * 16;
        for (int p = t; p < 800; p += NTHR) {
            int f = p >> 2, c = p & 3;
            float4 v = *(const float4*)(g_d1 + (size_t)f * BSZ + b0 + c * 4);
            sm.p6.d1s[f][c * 4 + 0] = v.x; sm.p6.d1s[f][c * 4 + 1] = v.y;
            sm.p6.d1s[f][c * 4 + 2] = v.z; sm.p6.d1s[f][c * 4 + 3] = v.w;
        }
        float acc[8];
        {
            float bb = (t < 160) ? bm2[t % 80] : 0.f;
#pragma unroll
            for (int r = 0; r < 8; r++) acc[r] = bb;
        }
        for (int j0 = 0; j0 < 200; j0 += 20) {
            __syncthreads();
            for (int p = t; p < 400; p += NTHR) {
                int row = p / 20, c4 = p - row * 20;
                *(float4*)&sm.p6.Ws2[row][c4 * 4] = *(const float4*)(Wm2 + (j0 + row) * 80 + c4 * 4);
            }
            __syncthreads();
            if (t < 160) {
                int f = t % 80, grp = t / 80;
#pragma unroll
                for (int jj = 0; jj < 20; jj++) {
                    float w = sm.p6.Ws2[jj][f];
#pragma unroll
                    for (int r = 0; r < 8; r++) acc[r] += w * sm.p6.d1s[j0 + jj][grp * 8 + r];
                }
            }
        }
        __syncthreads();
        if (t < 160) {
            int f = t % 80, grp = t / 80;
#pragma unroll
            for (int r = 0; r < 8; r++) sm.p6.ys[f][grp * 8 + r] = acc[r];
        }
        __syncthreads();
        {
            int w = t >> 5, lane = t & 31;
#pragma unroll
            for (int rep = 0; rep < 2; rep++) {
                int bl = w + rep * 8;
                float smv = 0.f, sq = 0.f;
                for (int c = lane; c < 80; c += 32) { float v = sm.p6.ys[c][bl]; smv += v; sq += v * v; }
#pragma unroll
                for (int o = 16; o; o >>= 1) {
                    smv += __shfl_down_sync(0xffffffffu, smv, o);
                    sq  += __shfl_down_sync(0xffffffffu, sq, o);
                }
                if (lane == 0) {
                    float mu = smv * (1.f / 80.f);
                    float var = sq * (1.f / 80.f) - mu * mu;
                    sm.p6.mu[bl] = mu; sm.p6.is[bl] = rsqrtf(var + 1e-3f);
                }
            }
        }
        __syncthreads();
        if (t < 160) {
            int f = t % 80, grp = t / 80;
            float gg = gl2[f], be = bl2[f];
#pragma unroll
            for (int r = 0; r < 8; r++) {
                int bl = grp * 8 + r;
                g_y2[(size_t)f * BSZ + b0 + bl] = (sm.p6.ys[f][bl] - sm.p6.mu[bl]) * sm.p6.is[bl] * gg + be;
            }
        }
    }
    gbar();

    // ---------------- P7: stats2 + dice + out GEMM + softmax ----------------
    if (bid < 32) {
        int w = t >> 5, lane = t & 31;
        int b0 = bid * 16;
        if (t < 160) sm.p7.Wsh[t] = Wo[t];
        if (t < 80) sm.p7.Ash[t] = al2[t];
        for (int r = 0; r < 10; r++) {
            int f = w * 10 + r;
            const float4* row = (const float4*)(g_y2 + (size_t)f * BSZ);
            float smv = 0.f, sq = 0.f;
#pragma unroll
            for (int i = 0; i < 4; i++) {
                float4 v = row[lane + 32 * i];
                smv += v.x + v.y + v.z + v.w;
                sq += v.x * v.x + v.y * v.y + v.z * v.z + v.w * v.w;
            }
#pragma unroll
            for (int o = 16; o; o >>= 1) {
                smv += __shfl_down_sync(0xffffffffu, smv, o);
                sq  += __shfl_down_sync(0xffffffffu, sq, o);
            }
            if (lane == 0) {
                float mu = smv * (1.f / 512.f);
                float var = sq * (1.f / 512.f) - mu * mu;
                sm.p7.mu[f] = mu; sm.p7.is[f] = rsqrtf(var + 1e-3f);
            }
        }
        __syncthreads();
        float bo0 = bo[0], bo1 = bo[1];
#pragma unroll
        for (int rep = 0; rep < 2; rep++) {
            int b = b0 + w + rep * 8;
            float a0 = 0.f, a1 = 0.f;
            for (int f = lane; f < 80; f += 32) {
                float v = g_y2[(size_t)f * BSZ + b];
                float xn = (v - sm.p7.mu[f]) * sm.p7.is[f];
                float p = sigm(xn);
                float h = v * (p + sm.p7.Ash[f] * (1.f - p));
                a0 += h * sm.p7.Wsh[2 * f];
                a1 += h * sm.p7.Wsh[2 * f + 1];
            }
#pragma unroll
            for (int o = 16; o; o >>= 1) {
                a0 += __shfl_down_sync(0xffffffffu, a0, o);
                a1 += __shfl_down_sync(0xffffffffu, a1, o);
            }
            if (lane == 0) {
                a0 += bo0; a1 += bo1;
                float m = fmaxf(a0, a1);
                float e0 = __expf(a0 - m), e1 = __expf(a1 - m);
                float inv = __fdividef(1.f, e0 + e1);
                out[b * 2] = e0 * inv;
                out[b * 2 + 1] = e1 * inv;
            }
        }
    }
}

// ============================================================================
extern "C" void kernel_launch(void* const* d_in, const int* in_sizes, int n_in,
                              void* d_out, int out_size) {
    (void)in_sizes; (void)n_in; (void)out_size;
    const int* uid  = (const int*)d_in[0];
    const int* ut1  = (const int*)d_in[1];
    const int* ut2  = (const int*)d_in[2];
    const int* ut3  = (const int*)d_in[3];
    const int* ut4  = (const int*)d_in[4];
    const int* ig   = (const int*)d_in[5];
    const int* ish  = (const int*)d_in[6];
    const int* ic   = (const int*)d_in[7];
    const int* vg   = (const int*)d_in[8];
    const int* vsh  = (const int*)d_in[9];
    const int* vc   = (const int*)d_in[10];
    const float* table     = (const float*)d_in[11];
    const float* W_act1    = (const float*)d_in[12];
    const float* b_act1    = (const float*)d_in[13];
    const float* alpha_act = (const float*)d_in[14];
    const float* W_act_out = (const float*)d_in[15];
    const float* b_act_out = (const float*)d_in[16];
    const float* W_mlp1    = (const float*)d_in[17];
    const float* b_mlp1    = (const float*)d_in[18];
    const float* g_ln1     = (const float*)d_in[19];
    const float* beta_ln1  = (const float*)d_in[20];
    const float* alpha_m1  = (const float*)d_in[21];
    const float* W_mlp2    = (const float*)d_in[22];
    const float* b_mlp2    = (const float*)d_in[23];
    const float* g_ln2     = (const float*)d_in[24];
    const float* beta_ln2  = (const float*)d_in[25];
    const float* alpha_m2  = (const float*)d_in[26];
    const float* W_out     = (const float*)d_in[27];
    const float* b_out     = (const float*)d_in[28];
    float* out = (float*)d_out;

    IdPtrs ids;
    ids.p[0] = uid; ids.p[1] = ut1; ids.p[2] = ut2; ids.p[3] = ut3;
    ids.p[4] = ut4; ids.p[5] = ig;  ids.p[6] = ish; ids.p[7] = ic;

    din_fused<<<NBLK, NTHR>>>(table, ids, vg, vsh, vc,
                              W_act1, b_act1, alpha_act, W_act_out, b_act_out,
                              W_mlp1, b_mlp1, g_ln1, beta_ln1, alpha_m1,
                              W_mlp2, b_mlp2, g_ln2, beta_ln2, alpha_m2,
                              W_out, b_out, out);
}

// round 7
// speedup vs baseline: 3.7000x; 1.4679x over previous
#include <cuda_runtime.h>
#include <math.h>

#define BSZ   512
#define SEQ   100
#define DIM   16
#define NH    36
#define ECOLS 1764        // 48*36 (E) + 36 (c)
#define COMB  176
#define NBLK  128
#define NTHR  256

// -------- scratch (__device__ globals: allocation-free) --------
__device__ __align__(16) float g_Ec[BSZ * ECOLS];      // [(i*9+kq)*2048 + b*4 + c]
__device__ __align__(16) float g_h[SEQ * NH * BSZ];    // [(s*36+k)*512 + b]
__device__ __align__(16) float g_coef[SEQ * BSZ];      // [s][b]
__device__ __align__(16) float g_y1[200 * BSZ];        // [f][b]
__device__ __align__(16) float g_d1[200 * BSZ];        // dice(y1) [f][b]
__device__ __align__(16) float g_y2[80 * BSZ];         // [f][b]
__device__ int g_skeep[SEQ];
__device__ unsigned g_cnt;
__device__ volatile unsigned g_gen;

struct IdPtrs { const int* p[8]; };

union SMem {
    struct { float As[48][64]; } p2;                                     // 12 KB
    struct { float mu[NH]; float is[NH]; } p3;
    struct { float xs[4][COMB]; float ys[4][201]; float mu[4]; float is[4];
             float csh[4]; } p4;                                         // ~6 KB
    struct { float red[16]; float mu, is; } p5;
    struct { float d1s[200][4]; float ys[80][5]; float mu[4]; float is[4]; } p6;
    struct { float mu[80]; float is[80]; float Wsh[160]; float Ash[80]; } p7;
};

__device__ __forceinline__ float sigm(float x) {
    return __fdividef(1.f, 1.f + __expf(-x));
}

// Software grid barrier (all NBLK=128 blocks co-resident on 148 SMs).
// Tight spin on a volatile generation counter — no nanosleep.
__device__ __forceinline__ void gbar() {
    __syncthreads();
    if (threadIdx.x == 0) {
        unsigned gen = g_gen;
        __threadfence();
        if (atomicAdd(&g_cnt, 1u) == NBLK - 1) {
            g_cnt = 0;
            __threadfence();
            g_gen = gen + 1;
        } else {
            while (g_gen == gen) {}
        }
    }
    __syncthreads();
}

__global__ __launch_bounds__(NTHR) void din_fused(
        const float* __restrict__ table, IdPtrs ids,
        const int* __restrict__ vg, const int* __restrict__ vsh,
        const int* __restrict__ vc,
        const float* __restrict__ W1, const float* __restrict__ b1,
        const float* __restrict__ alpha_a, const float* __restrict__ wout,
        const float* __restrict__ bout,
        const float* __restrict__ Wm1, const float* __restrict__ bm1,
        const float* __restrict__ gl1, const float* __restrict__ bl1,
        const float* __restrict__ al1,
        const float* __restrict__ Wm2, const float* __restrict__ bm2,
        const float* __restrict__ gl2, const float* __restrict__ bl2,
        const float* __restrict__ al2,
        const float* __restrict__ Wo, const float* __restrict__ bo,
        float* __restrict__ out) {
    __shared__ SMem sm;
    __shared__ int skeepS[SEQ];
    int bid = blockIdx.x;
    int t = threadIdx.x;

    // ---------------- P1: per-s keep mask ----------------
    if (bid < SEQ) {
        int any = 0;
        for (int b = t; b < BSZ; b += NTHR) any |= (vg[b * SEQ + bid] == 0);
        int r = __syncthreads_or(any);
        if (t == 0) g_skeep[bid] = r;
    }
    gbar();                                                   // barrier 1

    int anyL = 0;
    for (int i = t; i < SEQ; i += NTHR) { int v = g_skeep[i]; skeepS[i] = v; anyL |= v; }
    int anyAll = __syncthreads_or(anyL);   // uniform across blocks

    // ============ rare path: activation unit (3 extra barriers, uniform) ======
    if (anyAll) {
        // ---- P2: E GEMM ----
        for (int tile = bid; tile < 448; tile += NBLK) {
            int cx = tile % 56, by = tile / 56;
            int b_base = by * 64;
            for (int p = t; p < 48 * 64; p += NTHR) {
                int j = p >> 6, bl = p & 63;
                int which = j >> 4;
                int id = ids.p[5 + which][b_base + bl];
                sm.p2.As[j][bl] = table[(size_t)id * DIM + (j & 15)];
            }
            __syncthreads();
            int tx = t & 31, ty = t >> 5;
            int col = cx * 32 + tx;
            if (col < ECOLS) {
                int b0 = ty * 8;
                float acc[8];
#pragma unroll
                for (int r = 0; r < 8; r++) acc[r] = 0.f;
                int ii, kk;
                if (col < 1728) {
                    ii = col / 36; kk = col - ii * 36;
                    const float* wp = W1 + (size_t)(144 + ii * 48) * 36 + kk;
#pragma unroll 4
                    for (int j = 0; j < 48; j++) {
                        float w = wp[j * 36];
                        float4 a0 = *(const float4*)&sm.p2.As[j][b0];
                        float4 a1 = *(const float4*)&sm.p2.As[j][b0 + 4];
                        acc[0] += w * a0.x; acc[1] += w * a0.y; acc[2] += w * a0.z; acc[3] += w * a0.w;
                        acc[4] += w * a1.x; acc[5] += w * a1.y; acc[6] += w * a1.z; acc[7] += w * a1.w;
                    }
                    float wcb = W1[(96 + ii) * 36 + kk] - W1[(48 + ii) * 36 + kk];
#pragma unroll
                    for (int r = 0; r < 8; r++) acc[r] += wcb;
                } else {
                    ii = 48; kk = col - 1728;
#pragma unroll 4
                    for (int j = 0; j < 48; j++) {
                        float w = W1[j * 36 + kk] + W1[(48 + j) * 36 + kk];
                        float4 a0 = *(const float4*)&sm.p2.As[j][b0];
                        float4 a1 = *(const float4*)&sm.p2.As[j][b0 + 4];
                        acc[0] += w * a0.x; acc[1] += w * a0.y; acc[2] += w * a0.z; acc[3] += w * a0.w;
                        acc[4] += w * a1.x; acc[5] += w * a1.y; acc[6] += w * a1.z; acc[7] += w * a1.w;
                    }
                    float bb = b1[kk];
#pragma unroll
                    for (int r = 0; r < 8; r++) acc[r] += bb;
                }
                int kq = kk >> 2, c = kk & 3;
                size_t base = (size_t)(ii * 9 + kq) * 2048 + c;
#pragma unroll
                for (int r = 0; r < 8; r++)
                    g_Ec[base + (size_t)(b_base + b0 + r) * 4] = acc[r];
            }
            __syncthreads();
        }
        gbar();

        // ---- P3a: h_pre for kept s ----
        for (int it = bid; it < 200; it += NBLK) {
            int s = it >> 1, half = it & 1;
            if (!skeepS[s]) continue;
            int b = half * 256 + t;
            int id0 = vg[b * SEQ + s];
            int id1 = vsh[b * SEQ + s];
            int id2 = vc[b * SEQ + s];
            float vs[48];
            {
                const float4* r = (const float4*)(table + (size_t)id0 * DIM);
                float4 a = r[0], bb = r[1], cc = r[2], dd = r[3];
                vs[0]=a.x; vs[1]=a.y; vs[2]=a.z; vs[3]=a.w;
                vs[4]=bb.x; vs[5]=bb.y; vs[6]=bb.z; vs[7]=bb.w;
                vs[8]=cc.x; vs[9]=cc.y; vs[10]=cc.z; vs[11]=cc.w;
                vs[12]=dd.x; vs[13]=dd.y; vs[14]=dd.z; vs[15]=dd.w;
                r = (const float4*)(table + (size_t)id1 * DIM);
                a = r[0]; bb = r[1]; cc = r[2]; dd = r[3];
                vs[16]=a.x; vs[17]=a.y; vs[18]=a.z; vs[19]=a.w;
                vs[20]=bb.x; vs[21]=bb.y; vs[22]=bb.z; vs[23]=bb.w;
                vs[24]=cc.x; vs[25]=cc.y; vs[26]=cc.z; vs[27]=cc.w;
                vs[28]=dd.x; vs[29]=dd.y; vs[30]=dd.z; vs[31]=dd.w;
                r = (const float4*)(table + (size_t)id2 * DIM);
                a = r[0]; bb = r[1]; cc = r[2]; dd = r[3];
                vs[32]=a.x; vs[33]=a.y; vs[34]=a.z; vs[35]=a.w;
                vs[36]=bb.x; vs[37]=bb.y; vs[38]=bb.z; vs[39]=bb.w;
                vs[40]=cc.x; vs[41]=cc.y; vs[42]=cc.z; vs[43]=cc.w;
                vs[44]=dd.x; vs[45]=dd.y; vs[46]=dd.z; vs[47]=dd.w;
            }
            const float4* E4 = (const float4*)g_Ec;
            float h[36];
#pragma unroll
            for (int kq = 0; kq < 9; kq++) {
                float4 cv = E4[(size_t)(432 + kq) * 512 + b];
                h[kq*4+0]=cv.x; h[kq*4+1]=cv.y; h[kq*4+2]=cv.z; h[kq*4+3]=cv.w;
            }
            for (int i = 0; i < 48; i++) {
                float v = vs[i];
#pragma unroll
                for (int kq = 0; kq < 9; kq++) {
                    float4 e = E4[(size_t)(i * 9 + kq) * 512 + b];
                    h[kq*4+0] += v * e.x; h[kq*4+1] += v * e.y;
                    h[kq*4+2] += v * e.z; h[kq*4+3] += v * e.w;
                }
            }
#pragma unroll
            for (int k = 0; k < 36; k++)
                g_h[(size_t)(s * NH + k) * BSZ + b] = h[k];
        }
        gbar();

        // ---- P3b: stats + dice + score + mask -> coef ----
        {
            float bout0 = bout[0];
            for (int it = bid; it < 200; it += NBLK) {
                int s = it >> 1, half = it & 1;
                if (!skeepS[s]) continue;
                int w = t >> 5, lane = t & 31;
                for (int k = w; k < NH; k += 8) {
                    const float4* row = (const float4*)(g_h + (size_t)(s * NH + k) * BSZ);
                    float smv = 0.f, sq = 0.f;
#pragma unroll
                    for (int i = 0; i < 4; i++) {
                        float4 v = row[lane + 32 * i];
                        smv += v.x + v.y + v.z + v.w;
                        sq += v.x * v.x + v.y * v.y + v.z * v.z + v.w * v.w;
                    }
#pragma unroll
                    for (int o = 16; o; o >>= 1) {
                        smv += __shfl_down_sync(0xffffffffu, smv, o);
                        sq  += __shfl_down_sync(0xffffffffu, sq, o);
                    }
                    if (lane == 0) {
                        float mu = smv * (1.f / 512.f);
                        float var = sq * (1.f / 512.f) - mu * mu;
                        sm.p3.mu[k] = mu; sm.p3.is[k] = rsqrtf(var + 1e-3f);
                    }
                }
                __syncthreads();
                int b = half * 256 + t;
                float accv = 0.f;
#pragma unroll 4
                for (int k = 0; k < NH; k++) {
                    float x = g_h[(size_t)(s * NH + k) * BSZ + b];
                    float xn = (x - sm.p3.mu[k]) * sm.p3.is[k];
                    float p = sigm(xn);
                    accv += wout[k] * x * (p + alpha_a[k] * (1.f - p));
                }
                int vgv = vg[b * SEQ + s];
                g_coef[s * BSZ + b] = (vgv == 0) ? (accv + bout0) : 0.f;
                __syncthreads();
            }
        }
        gbar();
    }

    // ---------------- P4: x build + MLP1 (sync-free LDG GEMM) + LN -> y1T -----
    {
        int b0 = bid * 4;
        for (int p = t; p < 4 * 128; p += NTHR) {
            int bl = p >> 7, f = p & 127;
            sm.p4.xs[bl][f] = table[(size_t)ids.p[f >> 4][b0 + bl] * DIM + (f & 15)];
        }
        if (t < 4 * 48) { int bl = t / 48, i = t - bl * 48; sm.p4.xs[bl][128 + i] = 0.f; }
        __syncthreads();

        if (anyAll) {
            for (int s = 0; s < SEQ; s++) {
                if (!skeepS[s]) continue;
                if (t < 4) sm.p4.csh[t] = g_coef[s * BSZ + b0 + t];
                __syncthreads();
                if (t < 4 * 48) {
                    int bl = t / 48, i = t - bl * 48;
                    float c = sm.p4.csh[bl];
                    if (c != 0.f) {
                        int which = i >> 4;
                        int id = (which == 0) ? vg[(b0 + bl) * SEQ + s]
                               : (which == 1) ? vsh[(b0 + bl) * SEQ + s]
                                              : vc[(b0 + bl) * SEQ + s];
                        sm.p4.xs[bl][128 + i] += c * table[(size_t)id * DIM + (i & 15)];
                    }
                }
                __syncthreads();
            }
        }

        if (t < 200) {
            float bb = bm1[t];
            float acc0 = bb, acc1 = bb, acc2 = bb, acc3 = bb;
            const float* wp = Wm1 + t;
#pragma unroll 8
            for (int j = 0; j < COMB; j++) {
                float w = wp[j * 200];
                acc0 += w * sm.p4.xs[0][j];
                acc1 += w * sm.p4.xs[1][j];
                acc2 += w * sm.p4.xs[2][j];
                acc3 += w * sm.p4.xs[3][j];
            }
            sm.p4.ys[0][t] = acc0; sm.p4.ys[1][t] = acc1;
            sm.p4.ys[2][t] = acc2; sm.p4.ys[3][t] = acc3;
        }
        __syncthreads();
        if (t < 128) {
            int w = t >> 5, lane = t & 31;
            float smv = 0.f, sq = 0.f;
            for (int c = lane; c < 200; c += 32) { float v = sm.p4.ys[w][c]; smv += v; sq += v * v; }
#pragma unroll
            for (int o = 16; o; o >>= 1) {
                smv += __shfl_down_sync(0xffffffffu, smv, o);
                sq  += __shfl_down_sync(0xffffffffu, sq, o);
            }
            if (lane == 0) {
                float mu = smv * (1.f / 200.f);
                float var = sq * (1.f / 200.f) - mu * mu;
                sm.p4.mu[w] = mu; sm.p4.is[w] = rsqrtf(var + 1e-3f);
            }
        }
        __syncthreads();
        if (t < 200) {
            float gg = gl1[t], be = bl1[t];
#pragma unroll
            for (int r = 0; r < 4; r++)
                g_y1[(size_t)t * BSZ + bid * 4 + r] =
                    (sm.p4.ys[r][t] - sm.p4.mu[r]) * sm.p4.is[r] * gg + be;
        }
    }
    gbar();                                                   // barrier 2

    // ---------------- P5: batch stats of y1 + dice -> d1 ----------------
    for (int f = bid; f < 200; f += NBLK) {
        int w = t >> 5, lane = t & 31;
        const float2* row = (const float2*)(g_y1 + (size_t)f * BSZ);
        float2 v = row[t];
        float smv = v.x + v.y, sq = v.x * v.x + v.y * v.y;
#pragma unroll
        for (int o = 16; o; o >>= 1) {
            smv += __shfl_down_sync(0xffffffffu, smv, o);
            sq  += __shfl_down_sync(0xffffffffu, sq, o);
        }
        if (lane == 0) { sm.p5.red[w] = smv; sm.p5.red[8 + w] = sq; }
        __syncthreads();
        if (t == 0) {
            float s2 = 0.f, q2 = 0.f;
            for (int j = 0; j < 8; j++) { s2 += sm.p5.red[j]; q2 += sm.p5.red[8 + j]; }
            float mu = s2 * (1.f / 512.f);
            float var = q2 * (1.f / 512.f) - mu * mu;
            sm.p5.mu = mu; sm.p5.is = rsqrtf(var + 1e-3f);
        }
        __syncthreads();
        float a = al1[f];
        float mu = sm.p5.mu, is = sm.p5.is;
        float p0 = sigm((v.x - mu) * is);
        float p1 = sigm((v.y - mu) * is);
        float2 d;
        d.x = v.x * (p0 + a * (1.f - p0));
        d.y = v.y * (p1 + a * (1.f - p1));
        ((float2*)(g_d1 + (size_t)f * BSZ))[t] = d;
        __syncthreads();
    }
    gbar();                                                   // barrier 3

    // ---------------- P6: MLP2 (sync-free LDG GEMM) + LN -> y2T, 4 b/block ----
    {
        int b0 = bid * 4;
        if (t < 200)
            *(float4*)&sm.p6.d1s[t][0] = *(const float4*)(g_d1 + (size_t)t * BSZ + b0);
        __syncthreads();

        if (t < 80) {
            float bb = bm2[t];
            float acc0 = bb, acc1 = bb, acc2 = bb, acc3 = bb;
            const float* wp = Wm2 + t;
#pragma unroll 8
            for (int j = 0; j < 200; j++) {
                float w = wp[j * 80];
                acc0 += w * sm.p6.d1s[j][0];
                acc1 += w * sm.p6.d1s[j][1];
                acc2 += w * sm.p6.d1s[j][2];
                acc3 += w * sm.p6.d1s[j][3];
            }
            sm.p6.ys[t][0] = acc0; sm.p6.ys[t][1] = acc1;
            sm.p6.ys[t][2] = acc2; sm.p6.ys[t][3] = acc3;
        }
        __syncthreads();
        if (t < 128) {
            int w = t >> 5, lane = t & 31;
            float smv = 0.f, sq = 0.f;
            for (int c = lane; c < 80; c += 32) { float v = sm.p6.ys[c][w]; smv += v; sq += v * v; }
#pragma unroll
            for (int o = 16; o; o >>= 1) {
                smv += __shfl_down_sync(0xffffffffu, smv, o);
                sq  += __shfl_down_sync(0xffffffffu, sq, o);
            }
            if (lane == 0) {
                float mu = smv * (1.f / 80.f);
                float var = sq * (1.f / 80.f) - mu * mu;
                sm.p6.mu[w] = mu; sm.p6.is[w] = rsqrtf(var + 1e-3f);
            }
        }
        __syncthreads();
        if (t < 80) {
            float gg = gl2[t], be = bl2[t];
#pragma unroll
            for (int r = 0; r < 4; r++)
                g_y2[(size_t)t * BSZ + b0 + r] =
                    (sm.p6.ys[t][r] - sm.p6.mu[r]) * sm.p6.is[r] * gg + be;
        }
    }
    gbar();                                                   // barrier 4

    // ---------------- P7: stats2 + dice + out GEMM + softmax ----------------
    if (bid < 32) {
        int w = t >> 5, lane = t & 31;
        int b0 = bid * 16;
        if (t < 160) sm.p7.Wsh[t] = Wo[t];
        if (t < 80) sm.p7.Ash[t] = al2[t];
        for (int r = 0; r < 10; r++) {
            int f = w * 10 + r;
            const float4* row = (const float4*)(g_y2 + (size_t)f * BSZ);
            float smv = 0.f, sq = 0.f;
#pragma unroll
            for (int i = 0; i < 4; i++) {
                float4 v = row[lane + 32 * i];
                smv += v.x + v.y + v.z + v.w;
                sq += v.x * v.x + v.y * v.y + v.z * v.z + v.w * v.w;
            }
#pragma unroll
            for (int o = 16; o; o >>= 1) {
                smv += __shfl_down_sync(0xffffffffu, smv, o);
                sq  += __shfl_down_sync(0xffffffffu, sq, o);
            }
            if (lane == 0) {
                float mu = smv * (1.f / 512.f);
                float var = sq * (1.f / 512.f) - mu * mu;
                sm.p7.mu[f] = mu; sm.p7.is[f] = rsqrtf(var + 1e-3f);
            }
        }
        __syncthreads();
        float bo0 = bo[0], bo1 = bo[1];
#pragma unroll
        for (int rep = 0; rep < 2; rep++) {
            int b = b0 + w + rep * 8;
            float a0 = 0.f, a1 = 0.f;
            for (int f = lane; f < 80; f += 32) {
                float v = g_y2[(size_t)f * BSZ + b];
                float xn = (v - sm.p7.mu[f]) * sm.p7.is[f];
                float p = sigm(xn);
                float h = v * (p + sm.p7.Ash[f] * (1.f - p));
                a0 += h * sm.p7.Wsh[2 * f];
                a1 += h * sm.p7.Wsh[2 * f + 1];
            }
#pragma unroll
            for (int o = 16; o; o >>= 1) {
                a0 += __shfl_down_sync(0xffffffffu, a0, o);
                a1 += __shfl_down_sync(0xffffffffu, a1, o);
            }
            if (lane == 0) {
                a0 += bo0; a1 += bo1;
                float m = fmaxf(a0, a1);
                float e0 = __expf(a0 - m), e1 = __expf(a1 - m);
                float inv = __fdividef(1.f, e0 + e1);
                out[b * 2] = e0 * inv;
                out[b * 2 + 1] = e1 * inv;
            }
        }
    }
}

// ============================================================================
extern "C" void kernel_launch(void* const* d_in, const int* in_sizes, int n_in,
                              void* d_out, int out_size) {
    (void)in_sizes; (void)n_in; (void)out_size;
    const int* uid  = (const int*)d_in[0];
    const int* ut1  = (const int*)d_in[1];
    const int* ut2  = (const int*)d_in[2];
    const int* ut3  = (const int*)d_in[3];
    const int* ut4  = (const int*)d_in[4];
    const int* ig   = (const int*)d_in[5];
    const int* ish  = (const int*)d_in[6];
    const int* ic   = (const int*)d_in[7];
    const int* vg   = (const int*)d_in[8];
    const int* vsh  = (const int*)d_in[9];
    const int* vc   = (const int*)d_in[10];
    const float* table     = (const float*)d_in[11];
    const float* W_act1    = (const float*)d_in[12];
    const float* b_act1    = (const float*)d_in[13];
    const float* alpha_act = (const float*)d_in[14];
    const float* W_act_out = (const float*)d_in[15];
    const float* b_act_out = (const float*)d_in[16];
    const float* W_mlp1    = (const float*)d_in[17];
    const float* b_mlp1    = (const float*)d_in[18];
    const float* g_ln1     = (const float*)d_in[19];
    const float* beta_ln1  = (const float*)d_in[20];
    const float* alpha_m1  = (const float*)d_in[21];
    const float* W_mlp2    = (const float*)d_in[22];
    const float* b_mlp2    = (const float*)d_in[23];
    const float* g_ln2     = (const float*)d_in[24];
    const float* beta_ln2  = (const float*)d_in[25];
    const float* alpha_m2  = (const float*)d_in[26];
    const float* W_out     = (const float*)d_in[27];
    const float* b_out     = (const float*)d_in[28];
    float* out = (float*)d_out;

    IdPtrs ids;
    ids.p[0] = uid; ids.p[1] = ut1; ids.p[2] = ut2; ids.p[3] = ut3;
    ids.p[4] = ut4; ids.p[5] = ig;  ids.p[6] = ish; ids.p[7] = ic;

    din_fused<<<NBLK, NTHR>>>(table, ids, vg, vsh, vc,
                              W_act1, b_act1, alpha_act, W_act_out, b_act_out,
                              W_mlp1, b_mlp1, g_ln1, beta_ln1, alpha_m1,
                              W_mlp2, b_mlp2, g_ln2, beta_ln2, alpha_m2,
                              W_out, b_out, out);
}